// round 1
// baseline (speedup 1.0000x reference)
#include <cuda_runtime.h>
#include <math.h>

// ---------------- scratch (static device memory; no allocation allowed) ----
#define NTOT (1<<20)                       // 4*64*64*64
__device__ float g_c1[NTOT];
__device__ float g_x1[NTOT];
__device__ float g_th[NTOT];
__device__ float g_ph[NTOT];
__device__ float g_gg[NTOT];
__device__ float g_op[4 * NTOT];           // [split][b][c][n]
__device__ float g_mm[4 * 4 * 4096];       // [split][b][n]
__device__ float g_ll[4 * 4 * 4096];
__device__ float g_y[NTOT];
__device__ float g_z[NTOT];
__device__ float g_c2[NTOT];
__device__ float g_scale[64];
__device__ float g_shift[64];

// ---------------- conv 3x3, pad=1, NCHW, 8 output channels per block -------
__global__ void conv3x3_kernel(const float* __restrict__ in,
                               const float* __restrict__ w,
                               const float* __restrict__ bias,
                               float* __restrict__ out)
{
    __shared__ float wsm[8 * 576];     // 8 co x (64 ci * 9)
    __shared__ float tile[18 * 18];

    int b   = blockIdx.z >> 3;
    int co0 = (blockIdx.z & 7) * 8;
    int h0  = blockIdx.y * 16;
    int w0  = blockIdx.x * 16;
    int tid = threadIdx.y * 16 + threadIdx.x;

    for (int i = tid; i < 8 * 576; i += 256) wsm[i] = w[co0 * 576 + i];

    float acc[8];
#pragma unroll
    for (int k = 0; k < 8; k++) acc[k] = bias ? bias[co0 + k] : 0.f;

    for (int ci = 0; ci < 64; ci++) {
        __syncthreads();
        const float* xp = in + ((b * 64 + ci) << 12);
        for (int i = tid; i < 324; i += 256) {
            int th = i / 18, tw = i % 18;
            int gh = h0 - 1 + th, gw = w0 - 1 + tw;
            float v = 0.f;
            if ((unsigned)gh < 64u && (unsigned)gw < 64u) v = xp[gh * 64 + gw];
            tile[i] = v;
        }
        __syncthreads();

        float t[9];
#pragma unroll
        for (int r = 0; r < 3; r++)
#pragma unroll
            for (int c = 0; c < 3; c++)
                t[r * 3 + c] = tile[(threadIdx.y + r) * 18 + threadIdx.x + c];

#pragma unroll
        for (int k = 0; k < 8; k++) {
            const float* wp = &wsm[k * 576 + ci * 9];
#pragma unroll
            for (int q = 0; q < 9; q++) acc[k] = fmaf(wp[q], t[q], acc[k]);
        }
    }

    int h = h0 + threadIdx.y, ww = w0 + threadIdx.x;
#pragma unroll
    for (int k = 0; k < 8; k++)
        out[((b * 64 + co0 + k) << 12) + h * 64 + ww] = acc[k];
}

// ---------------- BN stats (training mode, biased var) ----------------------
__global__ void bn_stats_kernel(const float* __restrict__ in,
                                const float* __restrict__ gamma,
                                const float* __restrict__ beta)
{
    int c = blockIdx.x;
    int tid = threadIdx.x;
    float s = 0.f, q = 0.f;
    for (int t = tid; t < 16384; t += 256) {
        int b = t >> 12, i = t & 4095;
        float v = in[((b * 64 + c) << 12) + i];
        s += v; q += v * v;
    }
    __shared__ float ss[256], qq[256];
    ss[tid] = s; qq[tid] = q;
    __syncthreads();
    for (int o = 128; o > 0; o >>= 1) {
        if (tid < o) { ss[tid] += ss[tid + o]; qq[tid] += qq[tid + o]; }
        __syncthreads();
    }
    if (tid == 0) {
        float mean = ss[0] * (1.f / 16384.f);
        float var  = qq[0] * (1.f / 16384.f) - mean * mean;
        float sc   = gamma[c] * rsqrtf(var + 1e-5f);
        g_scale[c] = sc;
        g_shift[c] = beta[c] - mean * sc;
    }
}

__global__ void bn_relu_kernel(const float* __restrict__ in, float* __restrict__ out)
{
    int idx = blockIdx.x * 256 + threadIdx.x;
    int c = (idx >> 12) & 63;
    float v = fmaf(in[idx], g_scale[c], g_shift[c]);
    out[idx] = fmaxf(v, 0.f);
}

// ---------------- flash attention, split over columns ----------------------
// grid (32 row-tiles, 4 splits, 4 batch), block 128 (1 thread = 1 query row)
__global__ void __launch_bounds__(128, 2)
attn_kernel(const float* __restrict__ th, const float* __restrict__ ph,
            const float* __restrict__ gg,
            float* __restrict__ op, float* __restrict__ mo, float* __restrict__ lo)
{
    __shared__ float phis[64 * 68];   // [j][c], stride 68 (16B aligned, low conflict)
    __shared__ float gs[64 * 68];

    int b = blockIdx.z, split = blockIdx.y;
    int row = blockIdx.x * 128 + threadIdx.x;
    int base = b * 64 * 4096;
    int tid = threadIdx.x;

    float tr[64];
#pragma unroll
    for (int c = 0; c < 64; c++) tr[c] = th[base + c * 4096 + row];

    float acc[64];
#pragma unroll
    for (int c = 0; c < 64; c++) acc[c] = 0.f;
    float m = -1e30f, l = 0.f;

    for (int tile = 0; tile < 16; tile++) {
        int m0 = split * 1024 + tile * 64;
        __syncthreads();
        for (int i = tid; i < 4096; i += 128) {
            int c = i >> 6, j = i & 63;
            float pv = ph[base + c * 4096 + m0 + j];
            float gv = gg[base + c * 4096 + m0 + j];
            phis[j * 68 + c] = pv;
            gs[j * 68 + c]   = gv;
        }
        __syncthreads();

        for (int ch = 0; ch < 4; ch++) {
            float s[16];
#pragma unroll
            for (int jj = 0; jj < 16; jj++) {
                const float4* p = (const float4*)&phis[(ch * 16 + jj) * 68];
                float a = 0.f;
#pragma unroll
                for (int q = 0; q < 16; q++) {
                    float4 v = p[q];
                    a = fmaf(tr[4 * q], v.x, a);
                    a = fmaf(tr[4 * q + 1], v.y, a);
                    a = fmaf(tr[4 * q + 2], v.z, a);
                    a = fmaf(tr[4 * q + 3], v.w, a);
                }
                s[jj] = a;
            }
            float mc = s[0];
#pragma unroll
            for (int jj = 1; jj < 16; jj++) mc = fmaxf(mc, s[jj]);
            float mn = fmaxf(m, mc);
            float sc = __expf(m - mn);
            m = mn;
            l *= sc;
#pragma unroll
            for (int c = 0; c < 64; c++) acc[c] *= sc;

#pragma unroll
            for (int jj = 0; jj < 16; jj++) {
                float pv = __expf(s[jj] - mn);
                l += pv;
                const float4* gp = (const float4*)&gs[(ch * 16 + jj) * 68];
#pragma unroll
                for (int q = 0; q < 16; q++) {
                    float4 v = gp[q];
                    acc[4 * q]     = fmaf(pv, v.x, acc[4 * q]);
                    acc[4 * q + 1] = fmaf(pv, v.y, acc[4 * q + 1]);
                    acc[4 * q + 2] = fmaf(pv, v.z, acc[4 * q + 2]);
                    acc[4 * q + 3] = fmaf(pv, v.w, acc[4 * q + 3]);
                }
            }
        }
    }

    int ob = ((split * 4 + b) * 64) * 4096;
#pragma unroll
    for (int c = 0; c < 64; c++) op[ob + c * 4096 + row] = acc[c];
    mo[(split * 4 + b) * 4096 + row] = m;
    lo[(split * 4 + b) * 4096 + row] = l;
}

// ---------------- combine split-K partials + finalize softmax --------------
__global__ void combine_kernel(const float* __restrict__ op,
                               const float* __restrict__ mo,
                               const float* __restrict__ lo,
                               float* __restrict__ y)
{
    int idx = blockIdx.x * 256 + threadIdx.x;   // (b*64 + c)*4096 + n
    int n = idx & 4095;
    int b = idx >> 18;
    float m0 = mo[(0 + b) * 4096 + n];
    float m1 = mo[(4 + b) * 4096 + n];
    float m2 = mo[(8 + b) * 4096 + n];
    float m3 = mo[(12 + b) * 4096 + n];
    float M = fmaxf(fmaxf(m0, m1), fmaxf(m2, m3));
    float w0 = __expf(m0 - M), w1 = __expf(m1 - M);
    float w2 = __expf(m2 - M), w3 = __expf(m3 - M);
    float L = w0 * lo[(0 + b) * 4096 + n] + w1 * lo[(4 + b) * 4096 + n]
            + w2 * lo[(8 + b) * 4096 + n] + w3 * lo[(12 + b) * 4096 + n];
    float v = w0 * op[idx] + w1 * op[idx + NTOT]
            + w2 * op[idx + 2 * NTOT] + w3 * op[idx + 3 * NTOT];
    y[idx] = v / L;
}

// ---------------- 1x1 W-conv + bias + residual ------------------------------
__global__ void w1x1_kernel(const float* __restrict__ y, const float* __restrict__ Ww,
                            const float* __restrict__ Wb, const float* __restrict__ x,
                            float* __restrict__ z)
{
    __shared__ float wsm[8 * 64];
    int b = blockIdx.z;
    int co0 = blockIdx.y * 8;
    int n = blockIdx.x * 256 + threadIdx.x;
    for (int i = threadIdx.x; i < 512; i += 256) wsm[i] = Ww[co0 * 64 + i];
    __syncthreads();

    float acc[8];
#pragma unroll
    for (int k = 0; k < 8; k++) acc[k] = 0.f;
    for (int ci = 0; ci < 64; ci++) {
        float v = y[((b * 64 + ci) << 12) + n];
#pragma unroll
        for (int k = 0; k < 8; k++) acc[k] = fmaf(wsm[k * 64 + ci], v, acc[k]);
    }
#pragma unroll
    for (int k = 0; k < 8; k++) {
        int o = ((b * 64 + co0 + k) << 12) + n;
        z[o] = acc[k] + Wb[co0 + k] + x[o];
    }
}

// ---------------- launch -----------------------------------------------------
extern "C" void kernel_launch(void* const* d_in, const int* in_sizes, int n_in,
                              void* d_out, int out_size)
{
    const float* x    = (const float*)d_in[0];
    const float* c1w  = (const float*)d_in[1];
    const float* bn1g = (const float*)d_in[2];
    const float* bn1b = (const float*)d_in[3];
    const float* thw  = (const float*)d_in[4];
    const float* thb  = (const float*)d_in[5];
    const float* phw  = (const float*)d_in[6];
    const float* phb  = (const float*)d_in[7];
    const float* gw   = (const float*)d_in[8];
    const float* gb   = (const float*)d_in[9];
    const float* Ww   = (const float*)d_in[10];
    const float* Wb   = (const float*)d_in[11];
    const float* c2w  = (const float*)d_in[12];
    const float* bn2g = (const float*)d_in[13];
    const float* bn2b = (const float*)d_in[14];
    float* out = (float*)d_out;

    float *c1, *x1, *th, *ph, *gg, *op, *mm, *ll, *y, *z, *c2;
    cudaGetSymbolAddress((void**)&c1, g_c1);
    cudaGetSymbolAddress((void**)&x1, g_x1);
    cudaGetSymbolAddress((void**)&th, g_th);
    cudaGetSymbolAddress((void**)&ph, g_ph);
    cudaGetSymbolAddress((void**)&gg, g_gg);
    cudaGetSymbolAddress((void**)&op, g_op);
    cudaGetSymbolAddress((void**)&mm, g_mm);
    cudaGetSymbolAddress((void**)&ll, g_ll);
    cudaGetSymbolAddress((void**)&y,  g_y);
    cudaGetSymbolAddress((void**)&z,  g_z);
    cudaGetSymbolAddress((void**)&c2, g_c2);

    dim3 cgrid(4, 4, 32), cblk(16, 16);

    // conv1 + BN + ReLU
    conv3x3_kernel<<<cgrid, cblk>>>(x, c1w, nullptr, c1);
    bn_stats_kernel<<<64, 256>>>(c1, bn1g, bn1b);
    bn_relu_kernel<<<4096, 256>>>(c1, x1);

    // projections
    conv3x3_kernel<<<cgrid, cblk>>>(x1, thw, thb, th);
    conv3x3_kernel<<<cgrid, cblk>>>(x1, phw, phb, ph);
    conv3x3_kernel<<<cgrid, cblk>>>(x1, gw, gb, gg);

    // attention (flash, split-4 over columns) + combine
    attn_kernel<<<dim3(32, 4, 4), 128>>>(th, ph, gg, op, mm, ll);
    combine_kernel<<<4096, 256>>>(op, mm, ll, y);

    // 1x1 conv + residual
    w1x1_kernel<<<dim3(16, 8, 4), 256>>>(y, Ww, Wb, x, z);

    // conv2 + BN + ReLU
    conv3x3_kernel<<<cgrid, cblk>>>(z, c2w, nullptr, c2);
    bn_stats_kernel<<<64, 256>>>(c2, bn2g, bn2b);
    bn_relu_kernel<<<4096, 256>>>(c2, out);
}

// round 2
// speedup vs baseline: 1.0251x; 1.0251x over previous
#include <cuda_runtime.h>
#include <math.h>

// ---------------- scratch (static device memory; no allocation allowed) ----
#define NTOT (1<<20)                       // 4*64*64*64
__device__ float g_c1[NTOT];
__device__ float g_x1[NTOT];
__device__ float g_th[NTOT];
__device__ float g_ph[NTOT];
__device__ float g_gg[NTOT];
__device__ float g_op[4 * NTOT];           // [split][b][c][n]
__device__ float g_mm[4 * 4 * 4096];       // [split][b][n]
__device__ float g_ll[4 * 4 * 4096];
__device__ float g_y[NTOT];
__device__ float g_z[NTOT];
__device__ float g_c2[NTOT];
__device__ float g_scale[64];
__device__ float g_shift[64];

// ---------------- conv 3x3, pad=1, NCHW --------------------------------------
// Block: 256 threads (16x16). Each thread computes a 2x2 spatial patch for
// 8 output channels (36 independent FMA chains). Tile: 32x32 output region.
// Grid: (2, 2, 4*8)  ->  (wtile, htile, b*8+cog)
__global__ void __launch_bounds__(256, 2)
conv3x3_kernel(const float* __restrict__ in,
               const float* __restrict__ w,
               const float* __restrict__ bias,
               float* __restrict__ out)
{
    __shared__ float wsm[8 * 576];     // 8 co x (64 ci * 9)
    __shared__ float tile[34 * 34];    // input tile with halo

    int b   = blockIdx.z >> 3;
    int co0 = (blockIdx.z & 7) * 8;
    int h0  = blockIdx.y * 32;
    int w0  = blockIdx.x * 32;
    int tx  = threadIdx.x, ty = threadIdx.y;
    int tid = ty * 16 + tx;

    for (int i = tid; i < 8 * 576; i += 256) wsm[i] = w[co0 * 576 + i];

    float acc[8][4];
#pragma unroll
    for (int k = 0; k < 8; k++) {
        float bv = bias ? bias[co0 + k] : 0.f;
#pragma unroll
        for (int p = 0; p < 4; p++) acc[k][p] = bv;
    }

    for (int ci = 0; ci < 64; ci++) {
        __syncthreads();
        const float* xp = in + ((b * 64 + ci) << 12);
        for (int i = tid; i < 1156; i += 256) {
            int th = i / 34, tw = i - th * 34;
            int gh = h0 - 1 + th, gw = w0 - 1 + tw;
            float v = 0.f;
            if ((unsigned)gh < 64u && (unsigned)gw < 64u) v = xp[gh * 64 + gw];
            tile[i] = v;
        }
        __syncthreads();

        // 4x4 input patch for this thread's 2x2 outputs
        float t[4][4];
#pragma unroll
        for (int r = 0; r < 4; r++)
#pragma unroll
            for (int c = 0; c < 4; c++)
                t[r][c] = tile[(2 * ty + r) * 34 + 2 * tx + c];

#pragma unroll
        for (int k = 0; k < 8; k++) {
            float wr[9];
#pragma unroll
            for (int q = 0; q < 9; q++) wr[q] = wsm[k * 576 + ci * 9 + q];
#pragma unroll
            for (int py = 0; py < 2; py++)
#pragma unroll
                for (int px = 0; px < 2; px++) {
                    float a = acc[k][py * 2 + px];
#pragma unroll
                    for (int r = 0; r < 3; r++)
#pragma unroll
                        for (int c = 0; c < 3; c++)
                            a = fmaf(wr[r * 3 + c], t[py + r][px + c], a);
                    acc[k][py * 2 + px] = a;
                }
        }
    }

    // coalesced float2 stores (each thread owns 2 consecutive w pixels)
#pragma unroll
    for (int k = 0; k < 8; k++) {
#pragma unroll
        for (int py = 0; py < 2; py++) {
            int h = h0 + 2 * ty + py, ww = w0 + 2 * tx;
            float2 v = make_float2(acc[k][py * 2], acc[k][py * 2 + 1]);
            *(float2*)&out[((b * 64 + co0 + k) << 12) + h * 64 + ww] = v;
        }
    }
}

// ---------------- BN stats (training mode, biased var) ----------------------
__global__ void bn_stats_kernel(const float* __restrict__ in,
                                const float* __restrict__ gamma,
                                const float* __restrict__ beta)
{
    int c = blockIdx.x;
    int tid = threadIdx.x;
    float s = 0.f, q = 0.f;
    for (int t = tid; t < 16384; t += 256) {
        int b = t >> 12, i = t & 4095;
        float v = in[((b * 64 + c) << 12) + i];
        s += v; q += v * v;
    }
    __shared__ float ss[256], qq[256];
    ss[tid] = s; qq[tid] = q;
    __syncthreads();
    for (int o = 128; o > 0; o >>= 1) {
        if (tid < o) { ss[tid] += ss[tid + o]; qq[tid] += qq[tid + o]; }
        __syncthreads();
    }
    if (tid == 0) {
        float mean = ss[0] * (1.f / 16384.f);
        float var  = qq[0] * (1.f / 16384.f) - mean * mean;
        float sc   = gamma[c] * rsqrtf(var + 1e-5f);
        g_scale[c] = sc;
        g_shift[c] = beta[c] - mean * sc;
    }
}

__global__ void bn_relu_kernel(const float* __restrict__ in, float* __restrict__ out)
{
    int idx = blockIdx.x * 256 + threadIdx.x;
    int c = (idx >> 12) & 63;
    float v = fmaf(in[idx], g_scale[c], g_shift[c]);
    out[idx] = fmaxf(v, 0.f);
}

// ---------------- flash attention, split over columns ----------------------
// grid (32 row-tiles, 4 splits, 4 batch), block 128 (1 thread = 1 query row)
__global__ void __launch_bounds__(128, 2)
attn_kernel(const float* __restrict__ th, const float* __restrict__ ph,
            const float* __restrict__ gg,
            float* __restrict__ op, float* __restrict__ mo, float* __restrict__ lo)
{
    __shared__ float phis[64 * 68];   // [j][c], stride 68 (16B aligned, low conflict)
    __shared__ float gs[64 * 68];

    int b = blockIdx.z, split = blockIdx.y;
    int row = blockIdx.x * 128 + threadIdx.x;
    int base = b * 64 * 4096;
    int tid = threadIdx.x;

    float tr[64];
#pragma unroll
    for (int c = 0; c < 64; c++) tr[c] = th[base + c * 4096 + row];

    float acc[64];
#pragma unroll
    for (int c = 0; c < 64; c++) acc[c] = 0.f;
    float m = -1e30f, l = 0.f;

    for (int tile = 0; tile < 16; tile++) {
        int m0 = split * 1024 + tile * 64;
        __syncthreads();
        for (int i = tid; i < 4096; i += 128) {
            int c = i >> 6, j = i & 63;
            float pv = ph[base + c * 4096 + m0 + j];
            float gv = gg[base + c * 4096 + m0 + j];
            phis[j * 68 + c] = pv;
            gs[j * 68 + c]   = gv;
        }
        __syncthreads();

        for (int ch = 0; ch < 4; ch++) {
            float s[16];
#pragma unroll
            for (int jj = 0; jj < 16; jj++) {
                const float4* p = (const float4*)&phis[(ch * 16 + jj) * 68];
                float a = 0.f;
#pragma unroll
                for (int q = 0; q < 16; q++) {
                    float4 v = p[q];
                    a = fmaf(tr[4 * q], v.x, a);
                    a = fmaf(tr[4 * q + 1], v.y, a);
                    a = fmaf(tr[4 * q + 2], v.z, a);
                    a = fmaf(tr[4 * q + 3], v.w, a);
                }
                s[jj] = a;
            }
            float mc = s[0];
#pragma unroll
            for (int jj = 1; jj < 16; jj++) mc = fmaxf(mc, s[jj]);
            float mn = fmaxf(m, mc);
            float sc = __expf(m - mn);
            m = mn;
            l *= sc;
#pragma unroll
            for (int c = 0; c < 64; c++) acc[c] *= sc;

#pragma unroll
            for (int jj = 0; jj < 16; jj++) {
                float pv = __expf(s[jj] - mn);
                l += pv;
                const float4* gp = (const float4*)&gs[(ch * 16 + jj) * 68];
#pragma unroll
                for (int q = 0; q < 16; q++) {
                    float4 v = gp[q];
                    acc[4 * q]     = fmaf(pv, v.x, acc[4 * q]);
                    acc[4 * q + 1] = fmaf(pv, v.y, acc[4 * q + 1]);
                    acc[4 * q + 2] = fmaf(pv, v.z, acc[4 * q + 2]);
                    acc[4 * q + 3] = fmaf(pv, v.w, acc[4 * q + 3]);
                }
            }
        }
    }

    int ob = ((split * 4 + b) * 64) * 4096;
#pragma unroll
    for (int c = 0; c < 64; c++) op[ob + c * 4096 + row] = acc[c];
    mo[(split * 4 + b) * 4096 + row] = m;
    lo[(split * 4 + b) * 4096 + row] = l;
}

// ---------------- combine split-K partials + finalize softmax --------------
__global__ void combine_kernel(const float* __restrict__ op,
                               const float* __restrict__ mo,
                               const float* __restrict__ lo,
                               float* __restrict__ y)
{
    int idx = blockIdx.x * 256 + threadIdx.x;   // (b*64 + c)*4096 + n
    int n = idx & 4095;
    int b = idx >> 18;
    float m0 = mo[(0 + b) * 4096 + n];
    float m1 = mo[(4 + b) * 4096 + n];
    float m2 = mo[(8 + b) * 4096 + n];
    float m3 = mo[(12 + b) * 4096 + n];
    float M = fmaxf(fmaxf(m0, m1), fmaxf(m2, m3));
    float w0 = __expf(m0 - M), w1 = __expf(m1 - M);
    float w2 = __expf(m2 - M), w3 = __expf(m3 - M);
    float L = w0 * lo[(0 + b) * 4096 + n] + w1 * lo[(4 + b) * 4096 + n]
            + w2 * lo[(8 + b) * 4096 + n] + w3 * lo[(12 + b) * 4096 + n];
    float v = w0 * op[idx] + w1 * op[idx + NTOT]
            + w2 * op[idx + 2 * NTOT] + w3 * op[idx + 3 * NTOT];
    y[idx] = v / L;
}

// ---------------- 1x1 W-conv + bias + residual ------------------------------
__global__ void w1x1_kernel(const float* __restrict__ y, const float* __restrict__ Ww,
                            const float* __restrict__ Wb, const float* __restrict__ x,
                            float* __restrict__ z)
{
    __shared__ float wsm[8 * 64];
    int b = blockIdx.z;
    int co0 = blockIdx.y * 8;
    int n = blockIdx.x * 256 + threadIdx.x;
    for (int i = threadIdx.x; i < 512; i += 256) wsm[i] = Ww[co0 * 64 + i];
    __syncthreads();

    float acc[8];
#pragma unroll
    for (int k = 0; k < 8; k++) acc[k] = 0.f;
    for (int ci = 0; ci < 64; ci++) {
        float v = y[((b * 64 + ci) << 12) + n];
#pragma unroll
        for (int k = 0; k < 8; k++) acc[k] = fmaf(wsm[k * 64 + ci], v, acc[k]);
    }
#pragma unroll
    for (int k = 0; k < 8; k++) {
        int o = ((b * 64 + co0 + k) << 12) + n;
        z[o] = acc[k] + Wb[co0 + k] + x[o];
    }
}

// ---------------- launch -----------------------------------------------------
extern "C" void kernel_launch(void* const* d_in, const int* in_sizes, int n_in,
                              void* d_out, int out_size)
{
    const float* x    = (const float*)d_in[0];
    const float* c1w  = (const float*)d_in[1];
    const float* bn1g = (const float*)d_in[2];
    const float* bn1b = (const float*)d_in[3];
    const float* thw  = (const float*)d_in[4];
    const float* thb  = (const float*)d_in[5];
    const float* phw  = (const float*)d_in[6];
    const float* phb  = (const float*)d_in[7];
    const float* gw   = (const float*)d_in[8];
    const float* gb   = (const float*)d_in[9];
    const float* Ww   = (const float*)d_in[10];
    const float* Wb   = (const float*)d_in[11];
    const float* c2w  = (const float*)d_in[12];
    const float* bn2g = (const float*)d_in[13];
    const float* bn2b = (const float*)d_in[14];
    float* out = (float*)d_out;

    float *c1, *x1, *th, *ph, *gg, *op, *mm, *ll, *y, *z, *c2;
    cudaGetSymbolAddress((void**)&c1, g_c1);
    cudaGetSymbolAddress((void**)&x1, g_x1);
    cudaGetSymbolAddress((void**)&th, g_th);
    cudaGetSymbolAddress((void**)&ph, g_ph);
    cudaGetSymbolAddress((void**)&gg, g_gg);
    cudaGetSymbolAddress((void**)&op, g_op);
    cudaGetSymbolAddress((void**)&mm, g_mm);
    cudaGetSymbolAddress((void**)&ll, g_ll);
    cudaGetSymbolAddress((void**)&y,  g_y);
    cudaGetSymbolAddress((void**)&z,  g_z);
    cudaGetSymbolAddress((void**)&c2, g_c2);

    dim3 cgrid(2, 2, 32), cblk(16, 16);

    // conv1 + BN + ReLU
    conv3x3_kernel<<<cgrid, cblk>>>(x, c1w, nullptr, c1);
    bn_stats_kernel<<<64, 256>>>(c1, bn1g, bn1b);
    bn_relu_kernel<<<4096, 256>>>(c1, x1);

    // projections
    conv3x3_kernel<<<cgrid, cblk>>>(x1, thw, thb, th);
    conv3x3_kernel<<<cgrid, cblk>>>(x1, phw, phb, ph);
    conv3x3_kernel<<<cgrid, cblk>>>(x1, gw, gb, gg);

    // attention (flash, split-4 over columns) + combine
    attn_kernel<<<dim3(32, 4, 4), 128>>>(th, ph, gg, op, mm, ll);
    combine_kernel<<<4096, 256>>>(op, mm, ll, y);

    // 1x1 conv + residual
    w1x1_kernel<<<dim3(16, 8, 4), 256>>>(y, Ww, Wb, x, z);

    // conv2 + BN + ReLU
    conv3x3_kernel<<<cgrid, cblk>>>(z, c2w, nullptr, c2);
    bn_stats_kernel<<<64, 256>>>(c2, bn2g, bn2b);
    bn_relu_kernel<<<4096, 256>>>(c2, out);
}